// round 9
// baseline (speedup 1.0000x reference)
#include <cuda_runtime.h>
#include <math.h>

#define NLIST 2048          // max gaussians supported
#define CHUNK 128

__device__ __forceinline__ float sigmoidf_(float x) {
    return 1.0f / (1.0f + expf(-x));
}

// One CTA per 16x8 tile. Fully fused: bbox cull -> full params -> blend.
__global__ __launch_bounds__(128, 1)
void fused_render_kernel(
    float* __restrict__ out,
    const float* __restrict__ means,      // (N,3)
    const float* __restrict__ scales,     // (N,3)
    const float* __restrict__ rots,       // (N,4)
    const float* __restrict__ opacities,  // (N,1)
    const float* __restrict__ features,   // (N,3)
    const float* __restrict__ pose,       // (4,4) row-major
    const float* __restrict__ focal_p,
    const float* __restrict__ cx_p,
    const float* __restrict__ cy_p,
    int N, int W, int H)
{
    __shared__ int   s_list [NLIST];   // per-warp segments
    __shared__ int   s_list2[NLIST];   // concatenated, global order
    __shared__ int   s_cnt[4];
    __shared__ float4 s_bb[CHUNK];     // (min_u,max_u,min_v,max_v)
    __shared__ float4 s_gm[CHUNK];     // (u,v,z,op)
    __shared__ float4 s_cv[CHUNK];     // (ia, ib+ic, id, -)
    __shared__ float4 s_cl[CHUNK];     // (r,g,b,-)

    const int tid  = threadIdx.y * blockDim.x + threadIdx.x;
    const int lane = tid & 31;
    const int w    = tid >> 5;

    const float f  = __ldg(focal_p);
    const float cx = __ldg(cx_p);
    const float cy = __ldg(cy_p);

    const float R00 = __ldg(pose+0), R01 = __ldg(pose+1), R02 = __ldg(pose+2),  t0 = __ldg(pose+3);
    const float R10 = __ldg(pose+4), R11 = __ldg(pose+5), R12 = __ldg(pose+6),  t1 = __ldg(pose+7);
    const float R20 = __ldg(pose+8), R21 = __ldg(pose+9), R22 = __ldg(pose+10), t2 = __ldg(pose+11);

    // Tile extent in pixel coords, with +1px guard band for the conservative
    // phase-1 cull (phase-2's exact bbox test is authoritative).
    const float tx0 = (float)(blockIdx.x * 16) - 1.0f;
    const float tx1 = (float)(blockIdx.x * 16) + 16.0f;
    const float ty0 = (float)(blockIdx.y * 8) - 1.0f;
    const float ty1 = (float)(blockIdx.y * 8) + 8.0f;

    // ---- Phase 1: bbox-only cull, order-preserving per-warp compaction ----
    const int PW = ((N + 127) / 128) * 32;
    int cnt = 0;
    for (int k = 0; k < PW; k += 32) {
        int n = w * PW + k + lane;
        bool pred = false;
        if (n < N) {
            float mx = means[n*3+0], my = means[n*3+1], mz = means[n*3+2];
            float pcx = R00*mx + R01*my + R02*mz + t0;
            float pcy = R10*mx + R11*my + R12*mz + t1;
            float z   = R20*mx + R21*my + R22*mz + t2;
            float u = __fdividef(pcx, z) * f + cx;
            float v = __fdividef(pcy, z) * f + cy;
            float smaxl = fmaxf(scales[n*3+0], fmaxf(scales[n*3+1], scales[n*3+2]));
            float r = __expf(smaxl) * f * __fdividef(3.0f, z);  // max(exp)=exp(max)
            float min_u = fmaxf(0.0f, truncf(u - r));
            float max_u = truncf(u + r);
            float min_v = fmaxf(0.0f, truncf(v - r));
            float max_v = truncf(v + r);
            // NaN -> false, matches reference mask semantics
            pred = (min_u <= tx1) && (max_u >= tx0) && (min_v <= ty1) && (max_v >= ty0);
        }
        unsigned msk = __ballot_sync(0xffffffffu, pred);
        if (pred)
            s_list[w * PW + cnt + __popc(msk & ((1u << lane) - 1u))] = n;
        cnt += __popc(msk);
    }
    if (lane == 0) s_cnt[w] = cnt;
    __syncthreads();

    // Concatenate the 4 ordered segments -> globally ordered list.
    int c0 = s_cnt[0], c1 = s_cnt[1], c2 = s_cnt[2], c3 = s_cnt[3];
    int off[4] = {0, c0, c0 + c1, c0 + c1 + c2};
    int K = c0 + c1 + c2 + c3;
    for (int seg = 0; seg < 4; seg++) {
        int sc = s_cnt[seg];
        for (int j = tid; j < sc; j += 128)
            s_list2[off[seg] + j] = s_list[seg * PW + j];
    }
    __syncthreads();

    // ---- Phase 2: chunked full-param compute + branchless per-pixel blend ----
    const int px = blockIdx.x * 16 + threadIdx.x;
    const int py = blockIdx.y * 8  + threadIdx.y;
    const bool valid = (px < W) && (py < H);
    const float pxf = (float)px;
    const float pyf = (float)py;

    float ir = 0.0f, ig = 0.0f, ibl = 0.0f;
    float alpha_buf = 0.0f;
    float depth_buf = __int_as_float(0x7f800000);  // +inf

    bool wdone = false;   // warp-uniform: all lanes saturated

    for (int base = 0; base < K; base += CHUNK) {
        int m = K - base;
        if (m > CHUNK) m = CHUNK;

        if (tid < m) {
            int n = s_list2[base + tid];

            float sc0 = expf(scales[n*3+0]);
            float sc1 = expf(scales[n*3+1]);
            float sc2 = expf(scales[n*3+2]);

            float qw = rots[n*4+0], qx = rots[n*4+1], qy = rots[n*4+2], qz = rots[n*4+3];
            float two_s = 2.0f / (qw*qw + qx*qx + qy*qy + qz*qz);
            float xx = qx*qx*two_s, xy = qx*qy*two_s, xz = qx*qz*two_s;
            float yw = qy*qw*two_s, yy = qy*qy*two_s, yz = qy*qz*two_s;
            float zw = qz*qw*two_s, zz = qz*qz*two_s, xw = qx*qw*two_s;
            float M00 = 1.0f-(yy+zz), M01 = xy-zw,       M02 = xz+yw;
            float M10 = xy+zw,        M11 = 1.0f-(xx+zz), M12 = yz-xw;
            float M20 = xz-yw,        M21 = yz+xw,        M22 = 1.0f-(xx+yy);

            float mx = means[n*3+0], my = means[n*3+1], mz = means[n*3+2];
            float pcx = R00*mx + R01*my + R02*mz + t0;
            float pcy = R10*mx + R11*my + R12*mz + t1;
            float z   = R20*mx + R21*my + R22*mz + t2;
            float u = pcx / z * f + cx;
            float v = pcy / z * f + cy;

            float J00 = f*R00 - cx*R20, J01 = f*R01 - cx*R21, J02 = f*R02 - cx*R22;
            float J10 = f*R10 - cy*R20, J11 = f*R11 - cy*R21, J12 = f*R12 - cy*R22;

            float V00 = (J00*M00 + J01*M10 + J02*M20) * sc0;
            float V01 = (J00*M01 + J01*M11 + J02*M21) * sc1;
            float V02 = (J00*M02 + J01*M12 + J02*M22) * sc2;
            float V10 = (J10*M00 + J11*M10 + J12*M20) * sc0;
            float V11 = (J10*M01 + J11*M11 + J12*M21) * sc1;
            float V12 = (J10*M02 + J11*M12 + J12*M22) * sc2;

            float inv_zz = 1.0f / (z * z);
            float a = (V00*V00 + V01*V01 + V02*V02) * inv_zz;
            float b = (V00*V10 + V01*V11 + V02*V12) * inv_zz;
            float d = (V10*V10 + V11*V11 + V12*V12) * inv_zz;

            float det = a*d - b*b;
            float ia  = d / det;
            float ibc = (-b - b) / det;
            float idd = a / det;

            float smax = fmaxf(sc0, fmaxf(sc1, sc2));
            float r = smax * f / z * 3.0f;
            float min_u = fmaxf(0.0f, truncf(u - r));
            float max_u = truncf(u + r);
            float min_v = fmaxf(0.0f, truncf(v - r));
            float max_v = truncf(v + r);

            s_bb[tid] = make_float4(min_u, max_u, min_v, max_v);
            s_gm[tid] = make_float4(u, v, z, sigmoidf_(opacities[n]));
            s_cv[tid] = make_float4(ia, ibc, idd, 0.0f);
            s_cl[tid] = make_float4(sigmoidf_(features[n*3+0]),
                                    sigmoidf_(features[n*3+1]),
                                    sigmoidf_(features[n*3+2]), 0.0f);
        }
        __syncthreads();

        if (!wdone) {
            // Branchless blend: only carried deps are alpha_buf/depth_buf/rgb.
            #pragma unroll 4
            for (int i = 0; i < m; i++) {
                float4 bb = s_bb[i];
                float4 gm = s_gm[i];
                float4 cv = s_cv[i];
                float4 cl = s_cl[i];

                float dx = pxf - gm.x;
                float dy = pyf - gm.y;
                float dist_sq = cv.x*dx*dx + cv.y*dx*dy + cv.z*dy*dy;
                float alpha = gm.w * __expf(-0.5f * dist_sq);

                bool in_box = (pxf >= bb.x) & (pxf <= bb.y) & (pyf >= bb.z) & (pyf <= bb.w);
                bool hit = in_box & (dist_sq < 9.0f) & (gm.z < depth_buf);

                float na = hit ? alpha * (1.0f - alpha_buf) : 0.0f;
                float om = 1.0f - na;
                ir  = ir  * om + cl.x * na;
                ig  = ig  * om + cl.y * na;
                ibl = ibl * om + cl.z * na;
                alpha_buf += na;
                depth_buf = hit ? gm.z : depth_buf;

                // Saturation early-out: remaining contribution <= 1e-5 absolute.
                if ((i & 15) == 15) {
                    if (__all_sync(0xffffffffu, (1.0f - alpha_buf) < 1e-5f)) {
                        wdone = true;
                        break;
                    }
                }
            }
            if (!wdone)
                wdone = __all_sync(0xffffffffu, (1.0f - alpha_buf) < 1e-5f);
        }

        // Barrier + CTA-wide early exit (uniform).
        if (__syncthreads_and((int)wdone)) break;
    }

    if (valid) {
        int bidx = (py * W + px) * 3;
        out[bidx + 0] = ir;
        out[bidx + 1] = ig;
        out[bidx + 2] = ibl;
    }
}

extern "C" void kernel_launch(void* const* d_in, const int* in_sizes, int n_in,
                              void* d_out, int out_size)
{
    const float* means     = (const float*)d_in[0];
    const float* scales    = (const float*)d_in[1];
    const float* rots      = (const float*)d_in[2];
    const float* opacities = (const float*)d_in[3];
    const float* features  = (const float*)d_in[4];
    const float* pose      = (const float*)d_in[5];
    const float* focal_p   = (const float*)d_in[6];
    const float* cx_p      = (const float*)d_in[7];
    const float* cy_p      = (const float*)d_in[8];

    int N = in_sizes[0] / 3;

    // Derive (square) image dims from output size: out = H*W*3 floats.
    int hw = out_size / 3;
    int W = (int)(sqrtf((float)hw) + 0.5f);
    int H = hw / W;

    dim3 blk(16, 8);
    dim3 grd((W + 15) / 16, (H + 7) / 8);

    fused_render_kernel<<<grd, blk>>>(
        (float*)d_out, means, scales, rots, opacities, features, pose,
        focal_p, cx_p, cy_p, N, W, H);
}

// round 10
// speedup vs baseline: 1.6791x; 1.6791x over previous
#include <cuda_runtime.h>
#include <math.h>

#define NLIST 2048          // max gaussians supported
#define CHUNK 128

__device__ __forceinline__ float sigmoidf_(float x) {
    return 1.0f / (1.0f + expf(-x));
}

// One CTA per 16x8 tile. Fully fused: bbox cull -> full params -> blend.
__global__ __launch_bounds__(128, 1)
void fused_render_kernel(
    float* __restrict__ out,
    const float* __restrict__ means,      // (N,3)
    const float* __restrict__ scales,     // (N,3)
    const float* __restrict__ rots,       // (N,4)
    const float* __restrict__ opacities,  // (N,1)
    const float* __restrict__ features,   // (N,3)
    const float* __restrict__ pose,       // (4,4) row-major
    const float* __restrict__ focal_p,
    const float* __restrict__ cx_p,
    const float* __restrict__ cy_p,
    int N, int W, int H)
{
    __shared__ int   s_list [NLIST];   // per-warp segments
    __shared__ int   s_list2[NLIST];   // concatenated, global order
    __shared__ int   s_cnt[4];
    __shared__ float4 s_bb[CHUNK];     // (min_u,max_u,min_v,max_v)
    __shared__ float4 s_gm[CHUNK];     // (u,v,z,op)
    __shared__ float4 s_cv[CHUNK];     // (ia, ib+ic, id, -)
    __shared__ float4 s_cl[CHUNK];     // (r,g,b,-)

    const int tid  = threadIdx.y * blockDim.x + threadIdx.x;
    const int lane = tid & 31;
    const int w    = tid >> 5;

    const float f  = __ldg(focal_p);
    const float cx = __ldg(cx_p);
    const float cy = __ldg(cy_p);

    const float R00 = __ldg(pose+0), R01 = __ldg(pose+1), R02 = __ldg(pose+2),  t0 = __ldg(pose+3);
    const float R10 = __ldg(pose+4), R11 = __ldg(pose+5), R12 = __ldg(pose+6),  t1 = __ldg(pose+7);
    const float R20 = __ldg(pose+8), R21 = __ldg(pose+9), R22 = __ldg(pose+10), t2 = __ldg(pose+11);

    // Tile extent in pixel coords.
    const float tx0 = (float)(blockIdx.x * 16);
    const float tx1 = tx0 + 15.0f;
    const float ty0 = (float)(blockIdx.y * 8);
    const float ty1 = ty0 + 7.0f;

    // ---- Phase 1: bbox-only cull, order-preserving per-warp compaction ----
    const int PW = ((N + 127) / 128) * 32;
    int cnt = 0;
    for (int k = 0; k < PW; k += 32) {
        int n = w * PW + k + lane;
        bool pred = false;
        if (n < N) {
            float mx = means[n*3+0], my = means[n*3+1], mz = means[n*3+2];
            float pcx = R00*mx + R01*my + R02*mz + t0;
            float pcy = R10*mx + R11*my + R12*mz + t1;
            float z   = R20*mx + R21*my + R22*mz + t2;
            float u = pcx / z * f + cx;
            float v = pcy / z * f + cy;
            float smaxl = fmaxf(scales[n*3+0], fmaxf(scales[n*3+1], scales[n*3+2]));
            float r = __expf(smaxl) * f / z * 3.0f;   // exp monotonic: max(exp)=exp(max)
            float min_u = fmaxf(0.0f, truncf(u - r));
            float max_u = truncf(u + r);
            float min_v = fmaxf(0.0f, truncf(v - r));
            float max_v = truncf(v + r);
            // NaN -> false, matches reference mask semantics
            pred = (min_u <= tx1) && (max_u >= tx0) && (min_v <= ty1) && (max_v >= ty0);
        }
        unsigned msk = __ballot_sync(0xffffffffu, pred);
        if (pred)
            s_list[w * PW + cnt + __popc(msk & ((1u << lane) - 1u))] = n;
        cnt += __popc(msk);
    }
    if (lane == 0) s_cnt[w] = cnt;
    __syncthreads();

    // Concatenate the 4 ordered segments -> globally ordered list.
    int c0 = s_cnt[0], c1 = s_cnt[1], c2 = s_cnt[2], c3 = s_cnt[3];
    int off[4] = {0, c0, c0 + c1, c0 + c1 + c2};
    int K = c0 + c1 + c2 + c3;
    for (int seg = 0; seg < 4; seg++) {
        int sc = s_cnt[seg];
        for (int j = tid; j < sc; j += 128)
            s_list2[off[seg] + j] = s_list[seg * PW + j];
    }
    __syncthreads();

    // ---- Phase 2: chunked full-param compute + branchless per-pixel blend ----
    const int px = blockIdx.x * 16 + threadIdx.x;
    const int py = blockIdx.y * 8  + threadIdx.y;
    const bool valid = (px < W) && (py < H);
    const float pxf = (float)px;
    const float pyf = (float)py;

    float ir = 0.0f, ig = 0.0f, ibl = 0.0f;
    float alpha_buf = 0.0f;
    float depth_buf = __int_as_float(0x7f800000);  // +inf

    bool wdone = false;   // warp-uniform saturation flag (chunk granularity)

    for (int base = 0; base < K; base += CHUNK) {
        int m = K - base;
        if (m > CHUNK) m = CHUNK;

        if (tid < m) {
            int n = s_list2[base + tid];

            float sc0 = expf(scales[n*3+0]);
            float sc1 = expf(scales[n*3+1]);
            float sc2 = expf(scales[n*3+2]);

            float qw = rots[n*4+0], qx = rots[n*4+1], qy = rots[n*4+2], qz = rots[n*4+3];
            float two_s = 2.0f / (qw*qw + qx*qx + qy*qy + qz*qz);
            float xx = qx*qx*two_s, xy = qx*qy*two_s, xz = qx*qz*two_s;
            float yw = qy*qw*two_s, yy = qy*qy*two_s, yz = qy*qz*two_s;
            float zw = qz*qw*two_s, zz = qz*qz*two_s, xw = qx*qw*two_s;
            float M00 = 1.0f-(yy+zz), M01 = xy-zw,       M02 = xz+yw;
            float M10 = xy+zw,        M11 = 1.0f-(xx+zz), M12 = yz-xw;
            float M20 = xz-yw,        M21 = yz+xw,        M22 = 1.0f-(xx+yy);

            float mx = means[n*3+0], my = means[n*3+1], mz = means[n*3+2];
            float pcx = R00*mx + R01*my + R02*mz + t0;
            float pcy = R10*mx + R11*my + R12*mz + t1;
            float z   = R20*mx + R21*my + R22*mz + t2;
            float u = pcx / z * f + cx;
            float v = pcy / z * f + cy;

            float J00 = f*R00 - cx*R20, J01 = f*R01 - cx*R21, J02 = f*R02 - cx*R22;
            float J10 = f*R10 - cy*R20, J11 = f*R11 - cy*R21, J12 = f*R12 - cy*R22;

            float V00 = (J00*M00 + J01*M10 + J02*M20) * sc0;
            float V01 = (J00*M01 + J01*M11 + J02*M21) * sc1;
            float V02 = (J00*M02 + J01*M12 + J02*M22) * sc2;
            float V10 = (J10*M00 + J11*M10 + J12*M20) * sc0;
            float V11 = (J10*M01 + J11*M11 + J12*M21) * sc1;
            float V12 = (J10*M02 + J11*M12 + J12*M22) * sc2;

            float inv_zz = 1.0f / (z * z);
            float a = (V00*V00 + V01*V01 + V02*V02) * inv_zz;
            float b = (V00*V10 + V01*V11 + V02*V12) * inv_zz;
            float d = (V10*V10 + V11*V11 + V12*V12) * inv_zz;

            float det = a*d - b*b;
            float ia  = d / det;
            float ibc = (-b - b) / det;
            float idd = a / det;

            float smax = fmaxf(sc0, fmaxf(sc1, sc2));
            float r = smax * f / z * 3.0f;
            float min_u = fmaxf(0.0f, truncf(u - r));
            float max_u = truncf(u + r);
            float min_v = fmaxf(0.0f, truncf(v - r));
            float max_v = truncf(v + r);

            s_bb[tid] = make_float4(min_u, max_u, min_v, max_v);
            s_gm[tid] = make_float4(u, v, z, sigmoidf_(opacities[n]));
            s_cv[tid] = make_float4(ia, ibc, idd, 0.0f);
            s_cl[tid] = make_float4(sigmoidf_(features[n*3+0]),
                                    sigmoidf_(features[n*3+1]),
                                    sigmoidf_(features[n*3+2]), 0.0f);
        }
        __syncthreads();

        if (!wdone) {
            // Branchless blend loop (identical to R7): only carried deps are
            // alpha_buf/depth_buf/rgb. No control flow inside.
            #pragma unroll 4
            for (int i = 0; i < m; i++) {
                float4 bb = s_bb[i];
                float4 gm = s_gm[i];
                float4 cv = s_cv[i];
                float4 cl = s_cl[i];

                float dx = pxf - gm.x;
                float dy = pyf - gm.y;
                float dist_sq = cv.x*dx*dx + cv.y*dx*dy + cv.z*dy*dy;
                float alpha = gm.w * __expf(-0.5f * dist_sq);

                bool in_box = (pxf >= bb.x) & (pxf <= bb.y) & (pyf >= bb.z) & (pyf <= bb.w);
                bool hit = in_box & (dist_sq < 9.0f) & (gm.z < depth_buf);

                // na = hit ? alpha*(1-alpha_buf) : 0  (exact: miss leaves state unchanged)
                float na = hit ? alpha * (1.0f - alpha_buf) : 0.0f;
                float om = 1.0f - na;
                ir  = ir  * om + cl.x * na;
                ig  = ig  * om + cl.y * na;
                ibl = ibl * om + cl.z * na;
                alpha_buf += na;
                depth_buf = hit ? gm.z : depth_buf;
            }
            // One vote per chunk: remaining contribution <= 1e-5 absolute.
            wdone = __all_sync(0xffffffffu, (1.0f - alpha_buf) < 1e-5f);
        }

        // Barrier + CTA-wide early exit (uniform across CTA).
        if (__syncthreads_and((int)wdone)) break;
    }

    if (valid) {
        int bidx = (py * W + px) * 3;
        out[bidx + 0] = ir;
        out[bidx + 1] = ig;
        out[bidx + 2] = ibl;
    }
}

extern "C" void kernel_launch(void* const* d_in, const int* in_sizes, int n_in,
                              void* d_out, int out_size)
{
    const float* means     = (const float*)d_in[0];
    const float* scales    = (const float*)d_in[1];
    const float* rots      = (const float*)d_in[2];
    const float* opacities = (const float*)d_in[3];
    const float* features  = (const float*)d_in[4];
    const float* pose      = (const float*)d_in[5];
    const float* focal_p   = (const float*)d_in[6];
    const float* cx_p      = (const float*)d_in[7];
    const float* cy_p      = (const float*)d_in[8];

    int N = in_sizes[0] / 3;

    // Derive (square) image dims from output size: out = H*W*3 floats.
    int hw = out_size / 3;
    int W = (int)(sqrtf((float)hw) + 0.5f);
    int H = hw / W;

    dim3 blk(16, 8);
    dim3 grd((W + 15) / 16, (H + 7) / 8);

    fused_render_kernel<<<grd, blk>>>(
        (float*)d_out, means, scales, rots, opacities, features, pose,
        focal_p, cx_p, cy_p, N, W, H);
}